// round 15
// baseline (speedup 1.0000x reference)
#include <cuda_runtime.h>
#include <cstdint>

// Geometry (fixed by dataset): B=32, C=3, H=W=512
#define HW4_SHIFT 16
#define HW4       (1 << HW4_SHIFT)            // 65536 float4-groups per plane
#define NPIX_F    8388608.0f                  // 32*512*512 pixels

#define THREADS   256
#define NBLOCKS   8192                        // 1 float4-group per thread (R9 geometry)
#define NSLOTS    32
#define PER_SLOT  (NBLOCKS / NSLOTS)          // 256 blocks per slot-group

struct __align__(128) FSlot { float v;        float pad[31]; };
struct __align__(128) USlot { unsigned int v; unsigned int pad[31]; };
__device__ FSlot g_fslots[NSLOTS];            // float partials  (zero-init)
__device__ USlot g_subtick[NSLOTS];           // sub tickets     (zero-init)
__device__ __align__(128) unsigned int g_super;  // super ticket (zero-init)

// Hue in SIX-units: returns 6*h where h = (hue/6 mod 1). Range [0,6).
__device__ __forceinline__ float hue6(float r, float g, float b) {
    float maxc  = fmaxf(r, fmaxf(g, b));
    float minc  = fminf(r, fminf(g, b));
    float delta = maxc - minc;
    float safe  = (delta == 0.0f) ? 1.0f : delta;
    float inv;
    asm("rcp.approx.f32 %0, %1;" : "=f"(inv) : "f"(safe));

    float cr = (g - b) * inv;                 // [-1, 1]; ==0 when delta==0 (safe=1)
    float cg = fmaf(b - r, inv, 2.0f);        // [ 1, 3]
    float cb = fmaf(r - g, inv, 4.0f);        // [ 3, 5]

    // delta==0 -> maxc==r -> picks cr==0: matches reference's h=0 case for free.
    float h = (maxc == r) ? cr : ((maxc == g) ? cg : cb);
    return (h < 0.0f) ? h + 6.0f : h;         // mod 6 (only cr can be negative)
}

// Contribution in six-units; global 1/6 factor deferred to the final scale.
__device__ __forceinline__ float pix_loss6(float hp6, float ht6) {
    float d6 = fabsf(hp6 - ht6);
    return (d6 < 3.0f) ? d6 : (d6 - 3.0f);    // d6==3 contributes 0 either way
}

__global__ __launch_bounds__(THREADS)
void hsv_loss_onepass(const float4* __restrict__ pred,
                      const float4* __restrict__ targ,
                      float* __restrict__ out) {
    int gid = blockIdx.x * THREADS + threadIdx.x;   // one float4 group per thread
    int b   = gid >> HW4_SHIFT;
    int p4  = gid & (HW4 - 1);
    long long base = ((long long)b * 3) * HW4 + p4;

    // 6 independent LDG.128, front-batched
    float4 pr = pred[base];
    float4 pg = pred[base + HW4];
    float4 pb = pred[base + 2 * HW4];
    float4 tr = targ[base];
    float4 tg = targ[base + HW4];
    float4 tb = targ[base + 2 * HW4];

    float acc;
    acc  = pix_loss6(hue6(pr.x, pg.x, pb.x), hue6(tr.x, tg.x, tb.x));
    acc += pix_loss6(hue6(pr.y, pg.y, pb.y), hue6(tr.y, tg.y, tb.y));
    acc += pix_loss6(hue6(pr.z, pg.z, pb.z), hue6(tr.z, tg.z, tb.z));
    acc += pix_loss6(hue6(pr.w, pg.w, pb.w), hue6(tr.w, tg.w, tb.w));

    // ---- block reduce ----
    #pragma unroll
    for (int off = 16; off > 0; off >>= 1)
        acc += __shfl_xor_sync(0xFFFFFFFFu, acc, off);

    __shared__ float swarp[THREADS / 32];
    int lane = threadIdx.x & 31;
    int wid  = threadIdx.x >> 5;
    if (lane == 0) swarp[wid] = acc;
    __syncthreads();

    if (threadIdx.x == 0) {
        float v = (swarp[0] + swarp[1]) + (swarp[2] + swarp[3])
                + ((swarp[4] + swarp[5]) + (swarp[6] + swarp[7]));

        int slot = blockIdx.x & (NSLOTS - 1);

        // Fire-and-forget float add into a SPREAD slot (max 256 ops/address).
        asm volatile("red.global.gpu.add.f32 [%0], %1;"
                     :: "l"(&g_fslots[slot].v), "f"(v) : "memory");

        // Sub-ticket (SPREAD): release orders this block's red before it.
        unsigned int t;
        asm volatile("atom.release.gpu.global.add.u32 %0, [%1], 1;"
                     : "=r"(t) : "l"(&g_subtick[slot].v) : "memory");

        if (t == PER_SLOT - 1) {
            // Last of this slot-group: escalate (release chains the ordering).
            unsigned int s;
            asm volatile("atom.release.gpu.global.add.u32 %0, [%1], 1;"
                         : "=r"(s) : "l"(&g_super) : "memory");

            if (s == NSLOTS - 1) {            // exactly one thread in the grid
                asm volatile("fence.acq_rel.gpu;" ::: "memory");
                float sum = 0.0f;
                #pragma unroll
                for (int i = 0; i < NSLOTS; i++) {
                    float x;
                    asm volatile("ld.global.cv.f32 %0, [%1];"
                                 : "=f"(x) : "l"(&g_fslots[i].v));
                    sum += x;
                }
                out[0] = sum * (1.0f / (6.0f * NPIX_F));
                // reset for the next graph replay
                #pragma unroll
                for (int i = 0; i < NSLOTS; i++) {
                    asm volatile("st.global.cg.f32 [%0], 0f00000000;"
                                 :: "l"(&g_fslots[i].v) : "memory");
                    asm volatile("st.global.cg.u32 [%0], 0;"
                                 :: "l"(&g_subtick[i].v) : "memory");
                }
                asm volatile("st.global.cg.u32 [%0], 0;" :: "l"(&g_super) : "memory");
            }
        }
    }
}

extern "C" void kernel_launch(void* const* d_in, const int* in_sizes, int n_in,
                              void* d_out, int out_size) {
    const float4* pred = (const float4*)d_in[0];
    const float4* targ = (const float4*)d_in[1];
    float* out = (float*)d_out;
    hsv_loss_onepass<<<NBLOCKS, THREADS>>>(pred, targ, out);
}

// round 16
// speedup vs baseline: 1.2246x; 1.2246x over previous
#include <cuda_runtime.h>
#include <cstdint>

// Geometry (fixed by dataset): B=32, C=3, H=W=512
#define HW4_SHIFT 16
#define HW4       (1 << HW4_SHIFT)            // 65536 float4-groups per plane
#define NPIX_D    8388608.0                   // 32*512*512 pixels

#define THREADS   256
#define NBLOCKS   8192                        // 1 float4-group per thread (R9 geometry)

// Packed accumulator: bits [14..63] = fixed-point sum (x 2^20), bits [0..13] = count.
// Max sum = 8192 * 3072 * 2^20 ~= 2^58.6 ; count max 8192 < 2^14. No overflow.
__device__ unsigned long long g_pack;         // zero-init; reset by winner

// Hue in SIX-units: returns 6*h where h = (hue/6 mod 1). Range [0,6).
__device__ __forceinline__ float hue6(float r, float g, float b) {
    float maxc  = fmaxf(r, fmaxf(g, b));
    float minc  = fminf(r, fminf(g, b));
    float delta = maxc - minc;
    float safe  = (delta == 0.0f) ? 1.0f : delta;
    float inv;
    asm("rcp.approx.f32 %0, %1;" : "=f"(inv) : "f"(safe));

    float cr = (g - b) * inv;                 // [-1, 1]; ==0 when delta==0 (safe=1)
    float cg = fmaf(b - r, inv, 2.0f);        // [ 1, 3]
    float cb = fmaf(r - g, inv, 4.0f);        // [ 3, 5]

    // delta==0 -> maxc==r -> picks cr==0: matches reference's h=0 case for free.
    float h = (maxc == r) ? cr : ((maxc == g) ? cg : cb);
    return (h < 0.0f) ? h + 6.0f : h;         // mod 6 (only cr can be negative)
}

// Contribution in six-units; global 1/6 factor deferred to the final scale.
__device__ __forceinline__ float pix_loss6(float hp6, float ht6) {
    float d6 = fabsf(hp6 - ht6);
    return (d6 < 3.0f) ? d6 : (d6 - 3.0f);    // d6==3 contributes 0 either way
}

__global__ __launch_bounds__(THREADS)
void hsv_loss_onepass(const float4* __restrict__ pred,
                      const float4* __restrict__ targ,
                      float* __restrict__ out) {
    int gid = blockIdx.x * THREADS + threadIdx.x;   // one float4 group per thread
    int b   = gid >> HW4_SHIFT;
    int p4  = gid & (HW4 - 1);
    long long base = ((long long)b * 3) * HW4 + p4;

    // 6 independent LDG.128, front-batched
    float4 pr = pred[base];
    float4 pg = pred[base + HW4];
    float4 pb = pred[base + 2 * HW4];
    float4 tr = targ[base];
    float4 tg = targ[base + HW4];
    float4 tb = targ[base + 2 * HW4];

    float acc;
    acc  = pix_loss6(hue6(pr.x, pg.x, pb.x), hue6(tr.x, tg.x, tb.x));
    acc += pix_loss6(hue6(pr.y, pg.y, pb.y), hue6(tr.y, tg.y, tb.y));
    acc += pix_loss6(hue6(pr.z, pg.z, pb.z), hue6(tr.z, tg.z, tb.z));
    acc += pix_loss6(hue6(pr.w, pg.w, pb.w), hue6(tr.w, tg.w, tb.w));

    // ---- block reduce ----
    #pragma unroll
    for (int off = 16; off > 0; off >>= 1)
        acc += __shfl_xor_sync(0xFFFFFFFFu, acc, off);

    __shared__ float swarp[THREADS / 32];
    int lane = threadIdx.x & 31;
    int wid  = threadIdx.x >> 5;
    if (lane == 0) swarp[wid] = acc;
    __syncthreads();

    if (threadIdx.x == 0) {
        float v = (swarp[0] + swarp[1]) + (swarp[2] + swarp[3])
                + ((swarp[4] + swarp[5]) + (swarp[6] + swarp[7]));

        // Fixed-point encode (exact: v*2^20 < 2^32, double conversion exact).
        unsigned long long fx =
            (unsigned long long)__double2ll_rn((double)v * 1048576.0);
        unsigned long long pkt = (fx << 14) | 1ull;

        // ONE relaxed atomic carries both the partial sum and the arrival count.
        // No fences, no release, no separate visibility path needed.
        unsigned long long old;
        asm volatile("atom.relaxed.gpu.global.add.u64 %0, [%1], %2;"
                     : "=l"(old) : "l"(&g_pack), "l"(pkt) : "memory");

        if ((old & 0x3FFFull) == (unsigned long long)(NBLOCKS - 1)) {
            // Winner: 'old' already contains the exact sum of all other blocks.
            unsigned long long total = (old >> 14) + fx;
            out[0] = (float)((double)total * (1.0 / 1048576.0) / (6.0 * NPIX_D));
            // reset for the next graph replay (kernel boundary publishes this)
            asm volatile("st.global.cg.u64 [%0], 0;" :: "l"(&g_pack) : "memory");
        }
    }
}

extern "C" void kernel_launch(void* const* d_in, const int* in_sizes, int n_in,
                              void* d_out, int out_size) {
    const float4* pred = (const float4*)d_in[0];
    const float4* targ = (const float4*)d_in[1];
    float* out = (float*)d_out;
    hsv_loss_onepass<<<NBLOCKS, THREADS>>>(pred, targ, out);
}

// round 17
// speedup vs baseline: 1.2281x; 1.0029x over previous
#include <cuda_runtime.h>
#include <cstdint>

// Geometry (fixed by dataset): B=32, C=3, H=W=512
#define HW4_SHIFT 16
#define HW4       (1 << HW4_SHIFT)            // 65536 float4-groups per plane
#define NPIX_D    8388608.0                   // 32*512*512 pixels

#define THREADS   512
#define NWARPS    (THREADS / 32)
#define NBLOCKS   4096                        // 1 float4-group per thread

// Packed accumulator: bits [14..63] = fixed-point sum (x 2^20), bits [0..13] = count.
// Max sum = 4096 * 6144 * 2^20 ~= 2^58.6 ; count max 4096 < 2^14. No overflow.
__device__ unsigned long long g_pack;         // zero-init; reset by winner

// Hue in SIX-units: returns 6*h where h = (hue/6 mod 1). Range [0,6).
__device__ __forceinline__ float hue6(float r, float g, float b) {
    float maxc  = fmaxf(r, fmaxf(g, b));
    float minc  = fminf(r, fminf(g, b));
    float delta = maxc - minc;
    float safe  = (delta == 0.0f) ? 1.0f : delta;
    float inv;
    asm("rcp.approx.f32 %0, %1;" : "=f"(inv) : "f"(safe));

    float cr = (g - b) * inv;                 // [-1, 1]; ==0 when delta==0 (safe=1)
    float cg = fmaf(b - r, inv, 2.0f);        // [ 1, 3]
    float cb = fmaf(r - g, inv, 4.0f);        // [ 3, 5]

    // delta==0 -> maxc==r -> picks cr==0: matches reference's h=0 case for free.
    float h = (maxc == r) ? cr : ((maxc == g) ? cg : cb);
    return (h < 0.0f) ? h + 6.0f : h;         // mod 6 (only cr can be negative)
}

// Contribution in six-units; global 1/6 factor deferred to the final scale.
__device__ __forceinline__ float pix_loss6(float hp6, float ht6) {
    float d6 = fabsf(hp6 - ht6);
    return (d6 < 3.0f) ? d6 : (d6 - 3.0f);    // d6==3 contributes 0 either way
}

__global__ __launch_bounds__(THREADS)
void hsv_loss_onepass(const float4* __restrict__ pred,
                      const float4* __restrict__ targ,
                      float* __restrict__ out) {
    int gid = blockIdx.x * THREADS + threadIdx.x;   // one float4 group per thread
    int b   = gid >> HW4_SHIFT;
    int p4  = gid & (HW4 - 1);
    long long base = ((long long)b * 3) * HW4 + p4;

    // 6 independent LDG.128, front-batched
    float4 pr = pred[base];
    float4 pg = pred[base + HW4];
    float4 pb = pred[base + 2 * HW4];
    float4 tr = targ[base];
    float4 tg = targ[base + HW4];
    float4 tb = targ[base + 2 * HW4];

    float acc;
    acc  = pix_loss6(hue6(pr.x, pg.x, pb.x), hue6(tr.x, tg.x, tb.x));
    acc += pix_loss6(hue6(pr.y, pg.y, pb.y), hue6(tr.y, tg.y, tb.y));
    acc += pix_loss6(hue6(pr.z, pg.z, pb.z), hue6(tr.z, tg.z, tb.z));
    acc += pix_loss6(hue6(pr.w, pg.w, pb.w), hue6(tr.w, tg.w, tb.w));

    // ---- block reduce (16 warps) ----
    #pragma unroll
    for (int off = 16; off > 0; off >>= 1)
        acc += __shfl_xor_sync(0xFFFFFFFFu, acc, off);

    __shared__ float swarp[NWARPS];
    int lane = threadIdx.x & 31;
    int wid  = threadIdx.x >> 5;
    if (lane == 0) swarp[wid] = acc;
    __syncthreads();

    if (threadIdx.x == 0) {
        float v = 0.0f;
        #pragma unroll
        for (int w = 0; w < NWARPS; w++) v += swarp[w];

        // Fixed-point encode (exact: v*2^20 < 2^33, double conversion exact).
        unsigned long long fx =
            (unsigned long long)__double2ll_rn((double)v * 1048576.0);
        unsigned long long pkt = (fx << 14) | 1ull;

        // ONE relaxed atomic carries both the partial sum and the arrival count.
        unsigned long long old;
        asm volatile("atom.relaxed.gpu.global.add.u64 %0, [%1], %2;"
                     : "=l"(old) : "l"(&g_pack), "l"(pkt) : "memory");

        if ((old & 0x3FFFull) == (unsigned long long)(NBLOCKS - 1)) {
            // Winner: 'old' already contains the exact sum of all other blocks.
            unsigned long long total = (old >> 14) + fx;
            out[0] = (float)((double)total * (1.0 / 1048576.0) / (6.0 * NPIX_D));
            // reset for the next graph replay (kernel boundary publishes this)
            asm volatile("st.global.cg.u64 [%0], 0;" :: "l"(&g_pack) : "memory");
        }
    }
}

extern "C" void kernel_launch(void* const* d_in, const int* in_sizes, int n_in,
                              void* d_out, int out_size) {
    const float4* pred = (const float4*)d_in[0];
    const float4* targ = (const float4*)d_in[1];
    float* out = (float*)d_out;
    hsv_loss_onepass<<<NBLOCKS, THREADS>>>(pred, targ, out);
}